// round 16
// baseline (speedup 1.0000x reference)
#include <cuda_runtime.h>
#include <cuda_fp16.h>
#include <cstdint>

#define BATCH 2
#define SEQ 2048
#define DMODEL 1024
#define NHEADS 16
#define HDIM 64
#define MTOT (BATCH * SEQ)          // 4096

#define WSCALE 2048.0f
#define INV_WSCALE 4.8828125e-4f    // 2^-11

// ---------------------------------------------------------------------------
// Scratch (static device globals)
// ---------------------------------------------------------------------------
__device__ __align__(16) __half g_x16[MTOT * DMODEL];
__device__ __align__(16) __half g_WTh[4][DMODEL * DMODEL];         // (2048 W)^T fp16
__device__ __align__(16) float  g_bias3[3 * DMODEL];
__device__ __align__(16) __half g_Q16[BATCH * NHEADS * SEQ * HDIM];  // [B,H,S,Dh]
__device__ __align__(16) __half g_K16[BATCH * NHEADS * SEQ * HDIM];
__device__ __align__(16) __half g_V16[BATCH * NHEADS * SEQ * HDIM];
__device__ __align__(16) __half g_ctx16[MTOT * DMODEL];            // [B,S,D] fp16
__device__ __align__(16) uint32_t g_maskbits[SEQ * (SEQ / 32)];    // 1 bit/elem, 512 KB

// ---------------------------------------------------------------------------
// Helpers
// ---------------------------------------------------------------------------
__device__ __forceinline__ uint32_t smem_u32(const void* p) {
    uint32_t a;
    asm("{ .reg .u64 t; cvta.to.shared.u64 t, %1; cvt.u32.u64 %0, t; }" : "=r"(a) : "l"(p));
    return a;
}
__device__ __forceinline__ void ldsm_x4(uint32_t* r, uint32_t addr) {
    asm volatile("ldmatrix.sync.aligned.m8n8.x4.shared.b16 {%0,%1,%2,%3}, [%4];"
        : "=r"(r[0]), "=r"(r[1]), "=r"(r[2]), "=r"(r[3]) : "r"(addr));
}
__device__ __forceinline__ void ldsm_x4_t(uint32_t* r, uint32_t addr) {
    asm volatile("ldmatrix.sync.aligned.m8n8.x4.trans.shared.b16 {%0,%1,%2,%3}, [%4];"
        : "=r"(r[0]), "=r"(r[1]), "=r"(r[2]), "=r"(r[3]) : "r"(addr));
}
__device__ __forceinline__ void mma_f16(float* d, const uint32_t* a, const uint32_t* b) {
    asm volatile("mma.sync.aligned.m16n8k16.row.col.f32.f16.f16.f32 "
        "{%0,%1,%2,%3}, {%4,%5,%6,%7}, {%8,%9}, {%0,%1,%2,%3};"
        : "+f"(d[0]), "+f"(d[1]), "+f"(d[2]), "+f"(d[3])
        : "r"(a[0]), "r"(a[1]), "r"(a[2]), "r"(a[3]), "r"(b[0]), "r"(b[1]));
}
__device__ __forceinline__ uint32_t h2exp2(uint32_t x) {
    uint32_t r;
    asm volatile("ex2.approx.f16x2 %0, %1;" : "=r"(r) : "r"(x));
    return r;
}
#define CP_ASYNC16(dst_u32, src_gptr) \
    asm volatile("cp.async.cg.shared.global [%0], [%1], 16;" \
        :: "r"(dst_u32), "l"(__cvta_generic_to_global(src_gptr)) : "memory")
#define CP_COMMIT() asm volatile("cp.async.commit_group;" ::: "memory")
#define CP_WAIT1()  asm volatile("cp.async.wait_group 1;" ::: "memory")
#define CP_WAIT0()  asm volatile("cp.async.wait_group 0;" ::: "memory")

// ---------------------------------------------------------------------------
// Prep kernels (vectorized)
// ---------------------------------------------------------------------------
__global__ void to_half8(const float* __restrict__ X, __half* __restrict__ X16)
{
    int i = (blockIdx.x * blockDim.x + threadIdx.x) * 8;
    float4 f0 = *(const float4*)(X + i);
    float4 f1 = *(const float4*)(X + i + 4);
    __half2 h[4];
    h[0] = __floats2half2_rn(f0.x, f0.y);
    h[1] = __floats2half2_rn(f0.z, f0.w);
    h[2] = __floats2half2_rn(f1.x, f1.y);
    h[3] = __floats2half2_rn(f1.z, f1.w);
    *(uint4*)(X16 + i) = *(uint4*)h;
}

__global__ void transpose4(const float* __restrict__ W0, const float* __restrict__ W1,
                           const float* __restrict__ W2, const float* __restrict__ W3,
                           __half* __restrict__ ThBase)
{
    __shared__ float t[32][33];
    const int z = blockIdx.z;
    const float* W = (z == 0) ? W0 : (z == 1) ? W1 : (z == 2) ? W2 : W3;
    __half* Th = ThBase + (size_t)z * DMODEL * DMODEL;
    int bx = blockIdx.x * 32;
    int by = blockIdx.y * 32;
    int tx = threadIdx.x, ty = threadIdx.y;
    #pragma unroll
    for (int i = 0; i < 4; i++)
        t[ty + i * 8][tx] = W[(size_t)(by + ty + i * 8) * DMODEL + bx + tx];
    __syncthreads();
    #pragma unroll
    for (int i = 0; i < 4; i++) {
        float v = t[tx][ty + i * 8] * WSCALE;
        size_t o = (size_t)(bx + ty + i * 8) * DMODEL + by + tx;
        Th[o] = __float2half(v);
    }
}

__global__ void concat_bias(const float* __restrict__ a, const float* __restrict__ b,
                            const float* __restrict__ c, float* __restrict__ o)
{
    int i = blockIdx.x * blockDim.x + threadIdx.x;
    if (i < DMODEL) { o[i] = a[i]; o[i + DMODEL] = b[i]; o[i + 2 * DMODEL] = c[i]; }
}

// Pack int32 mask -> 1 bit/elem. One warp packs 128 elems via 4 coalesced ballots.
__global__ void mask_pack(const int* __restrict__ mask, uint32_t* __restrict__ bits)
{
    int gw = (blockIdx.x * blockDim.x + threadIdx.x) >> 5;
    int lane = threadIdx.x & 31;
    const int* p = mask + (size_t)gw * 128;
    uint32_t b0 = __ballot_sync(0xffffffffu, p[lane]      != 0);
    uint32_t b1 = __ballot_sync(0xffffffffu, p[lane + 32] != 0);
    uint32_t b2 = __ballot_sync(0xffffffffu, p[lane + 64] != 0);
    uint32_t b3 = __ballot_sync(0xffffffffu, p[lane + 96] != 0);
    if (lane == 0) {
        uint4 v; v.x = b0; v.y = b1; v.z = b2; v.w = b3;
        *(uint4*)(bits + (size_t)gw * 4) = v;
    }
}

// ---------------------------------------------------------------------------
// fp16 single-term GEMM (scaled), 512 threads, warp tile 16x64 (32 warps/SM).
// Tile 128x128, K-chunk 32, 2-stage cp.async.
// acc = A16 @ BTh^T (= 2048*A W^T); epilogue C = acc * 2^-11 + bias.
// ---------------------------------------------------------------------------
#define MKS 40
#define ARRB (128 * MKS * 2)                // 10240 B
#define MM1_SMEM (2 * 2 * ARRB)             // 40960 B

__global__ __launch_bounds__(512, 2)
void mm1(const __half* __restrict__ A16, const __half* __restrict__ BTh,
         const float* __restrict__ bias, int mode, float* __restrict__ Cf,
         __half* __restrict__ oQ, __half* __restrict__ oK, __half* __restrict__ oV)
{
    extern __shared__ char sm[];
    const uint32_t sb = smem_u32(sm);

    const int tid = threadIdx.x;
    const int wid = tid >> 5;
    const int lane = tid & 31;
    const int wm = wid & 7;            // 8 m-warps of 16 rows
    const int wn = wid >> 3;           // 2 n-warps of 64 cols
    const int bm = blockIdx.y * 128;
    const int bn = blockIdx.x * 128;

    const int wsel = bn >> 10;
    const __half* Bh = BTh + (size_t)wsel * DMODEL * DMODEL;
    const int rB = bn & 1023;

    // staging: 512 threads x 1 uint4 per array (128 rows x 4 segs)
    const int rr = tid >> 2, sg = tid & 3;

    auto issue = [&](int c, int st) {
        const int k0 = c * 32;
        uint32_t so = (rr * MKS + sg * 8) * 2;
        uint32_t dst = sb + st * 2 * ARRB + so;
        size_t ga = (size_t)(bm + rr) * DMODEL + k0 + sg * 8;
        size_t gb = (size_t)(rB + rr) * DMODEL + k0 + sg * 8;
        CP_ASYNC16(dst + 0 * ARRB, A16 + ga);
        CP_ASYNC16(dst + 1 * ARRB, Bh + gb);
        CP_COMMIT();
    };

    issue(0, 0);
    issue(1, 1);

    float acc[8][4];
    #pragma unroll
    for (int ni = 0; ni < 8; ni++)
        #pragma unroll
        for (int e = 0; e < 4; e++) acc[ni][e] = 0.0f;

    const int aRow = wm * 16 + (lane & 15);
    const int aK   = (lane >> 4) * 8;
    const int bRow = wn * 64 + ((lane >> 4) & 1) * 8 + (lane & 7);
    const int bK   = ((lane >> 3) & 1) * 8;

    const int NCH = DMODEL / 32;   // 32
    for (int c = 0; c < NCH; c++) {
        const int st = c & 1;
        if (c + 1 < NCH) { CP_WAIT1(); } else { CP_WAIT0(); }
        __syncthreads();

        const uint32_t uA  = sb + st * 2 * ARRB + 0 * ARRB;
        const uint32_t uBh = sb + st * 2 * ARRB + 1 * ARRB;

        #pragma unroll
        for (int s = 0; s < 2; s++) {
            uint32_t aF[4];
            {
                uint32_t off = (aRow * MKS + s * 16 + aK) * 2;
                ldsm_x4(aF, uA + off);
            }
            #pragma unroll
            for (int gh = 0; gh < 2; gh++) {
                uint32_t bH[2][4];
                #pragma unroll
                for (int j = 0; j < 2; j++) {
                    uint32_t off = ((bRow + (2 * gh + j) * 16) * MKS + s * 16 + bK) * 2;
                    ldsm_x4(bH[j], uBh + off);
                }
                #pragma unroll
                for (int j = 0; j < 2; j++) {
                    mma_f16(acc[4 * gh + 2 * j],     aF, bH[j]);
                    mma_f16(acc[4 * gh + 2 * j + 1], aF, bH[j] + 2);
                }
            }
        }

        __syncthreads();
        if (c + 2 < NCH) issue(c + 2, st);
    }

    // Epilogue: warp tile 16x64; rows rBase, rBase+8
    const int rBase = bm + wm * 16 + (lane >> 2);
    const int cBase = bn + wn * 64 + (lane & 3) * 2;
    #pragma unroll
    for (int ni = 0; ni < 8; ni++) {
        int col = cBase + ni * 8;
        float b0 = bias[col], b1 = bias[col + 1];
        #pragma unroll
        for (int half_ = 0; half_ < 2; half_++) {
            int m = rBase + half_ * 8;
            float v0 = acc[ni][half_ * 2 + 0] * INV_WSCALE + b0;
            float v1 = acc[ni][half_ * 2 + 1] * INV_WSCALE + b1;
            if (mode) {
                int n1 = col & 1023;
                int b = m >> 11, s = m & 2047;
                int h = n1 >> 6, d = n1 & 63;
                size_t o = ((size_t)((b << 4) + h) * SEQ + s) * HDIM + d;
                __half* dst = (wsel == 0) ? oQ : (wsel == 1) ? oK : oV;
                *(__half2*)(dst + o) = __floats2half2_rn(v0, v1);
            } else {
                float* dst = Cf + (size_t)m * DMODEL + col;
                dst[0] = v0; dst[1] = v1;
            }
        }
    }
}

// ---------------------------------------------------------------------------
// Flash attention (R15): fp16 single-term, fixed-max f16x2-EX2 softmax,
// bit-packed mask, 2-stage cp.async, 2 CTA/SM.
// ---------------------------------------------------------------------------
#define FSTR 72
#define FROWB (FSTR * 2)
#define FT_BYTES (64 * FSTR * 2)            // 9216
#define FLASH_SMEM (2 * 2 * FT_BYTES)       // 36864
#define SCALE_LOG2E 0.18033688011112042f    // 0.125 * log2(e)
#define MWORDS (SEQ / 32)                   // 64 words per row

__global__ __launch_bounds__(256, 2)
void flash_mma(const __half* __restrict__ Q16,
               const __half* __restrict__ K16, const __half* __restrict__ V16,
               const uint32_t* __restrict__ mbits, __half* __restrict__ ctx16)
{
    extern __shared__ char sm[];
    const uint32_t uKV = smem_u32(sm);

    const int tid = threadIdx.x;
    const int lane = tid & 31;
    const int w = tid >> 5;
    const int qt = blockIdx.x;
    const int bh = blockIdx.y;
    const size_t base = (size_t)bh * SEQ * HDIM;

    // Q overlay through stage buffers
    #pragma unroll
    for (int i = 0; i < 4; i++) {
        int lin = tid + i * 256;
        int r = lin >> 3, c = lin & 7;
        *(uint4*)(sm + r * FROWB + c * 16) =
            *(const uint4*)&Q16[base + (size_t)(qt * 128 + r) * HDIM + c * 8];
    }
    __syncthreads();

    uint32_t qf[4][4];
    #pragma unroll
    for (int kch = 0; kch < 4; kch++) {
        uint32_t off = (w * 16 + (lane & 15)) * FROWB + (kch * 16 + (lane >> 4) * 8) * 2;
        ldsm_x4(qf[kch], uKV + off);
    }
    __syncthreads();

    const __half* srcs[2] = { K16, V16 };
    auto issue = [&](int kt, int stage) {
        #pragma unroll
        for (int t = 0; t < 2; t++) {
            #pragma unroll
            for (int u = 0; u < 2; u++) {
                int lin = tid * 2 + u;
                int r = lin >> 3, c = lin & 7;
                uint32_t dst = uKV + (stage * 2 + t) * FT_BYTES + r * FROWB + c * 16;
                const __half* src = srcs[t] + base + (size_t)(kt * 64 + r) * HDIM + c * 8;
                CP_ASYNC16(dst, src);
            }
        }
        CP_COMMIT();
    };

    issue(0, 0);
    issue(1, 1);

    float O[8][4];
    #pragma unroll
    for (int j = 0; j < 8; j++)
        #pragma unroll
        for (int e = 0; e < 4; e++) O[j][e] = 0.0f;
    float l0 = 0.0f, l1 = 0.0f;

    const int q0 = qt * 128 + w * 16 + (lane >> 2);
    const int colOff = 2 * (lane & 3);
    const uint32_t* mrowA = mbits + (size_t)q0 * MWORDS;
    const uint32_t* mrowB = mbits + (size_t)(q0 + 8) * MWORDS;

    for (int kt = 0; kt < 32; kt++) {
        const int stage = kt & 1;
        if (kt + 1 < 32) { CP_WAIT1(); } else { CP_WAIT0(); }
        __syncthreads();

        const uint32_t uK_ = uKV + (stage * 2 + 0) * FT_BYTES;
        const uint32_t uV_ = uKV + (stage * 2 + 1) * FT_BYTES;

        float S[8][4];
        #pragma unroll
        for (int j = 0; j < 8; j++)
            #pragma unroll
            for (int e = 0; e < 4; e++) S[j][e] = 0.0f;

        const int rowN = ((lane >> 4) & 1) * 8 + (lane & 7);
        const int bKo  = ((lane >> 3) & 1) * 16;
        #pragma unroll
        for (int kch = 0; kch < 4; kch++) {
            uint32_t bk_[4][4];
            #pragma unroll
            for (int g = 0; g < 4; g++) {
                uint32_t off = (g * 16 + rowN) * FROWB + kch * 32 + bKo;
                ldsm_x4(bk_[g], uK_ + off);
            }
            #pragma unroll
            for (int g = 0; g < 4; g++) {
                mma_f16(S[2 * g],     qf[kch], bk_[g]);
                mma_f16(S[2 * g + 1], qf[kch], bk_[g] + 2);
            }
        }

        const uint32_t mA0 = mrowA[2 * kt], mA1 = mrowA[2 * kt + 1];
        const uint32_t mB0 = mrowB[2 * kt], mB1 = mrowB[2 * kt + 1];

        uint32_t aP[4][4];
        #pragma unroll
        for (int j = 0; j < 8; j++) {
            const uint32_t mAw = (j < 4) ? mA0 : mA1;
            const uint32_t mBw = (j < 4) ? mB0 : mB1;
            const int bit = (j & 3) * 8 + colOff;
            float f0 = ((mAw >> bit) & 1u)       ? S[j][0] * SCALE_LOG2E : -1e4f;
            float f1 = ((mAw >> (bit + 1)) & 1u) ? S[j][1] * SCALE_LOG2E : -1e4f;
            float f2 = ((mBw >> bit) & 1u)       ? S[j][2] * SCALE_LOG2E : -1e4f;
            float f3 = ((mBw >> (bit + 1)) & 1u) ? S[j][3] * SCALE_LOG2E : -1e4f;
            __half2 a01 = __floats2half2_rn(f0, f1);
            __half2 a23 = __floats2half2_rn(f2, f3);
            uint32_t p01 = h2exp2(*(uint32_t*)&a01);
            uint32_t p23 = h2exp2(*(uint32_t*)&a23);
            const int t = j >> 1, u = j & 1;
            aP[t][2 * u]     = p01;
            aP[t][2 * u + 1] = p23;
            float2 g01 = __half22float2(*(__half2*)&p01);
            float2 g23 = __half22float2(*(__half2*)&p23);
            l0 += g01.x + g01.y;
            l1 += g23.x + g23.y;
        }

        #pragma unroll
        for (int t = 0; t < 4; t++) {
            uint32_t rowOff = (t * 16 + (lane & 15)) * FROWB + (lane >> 4) * 16;
            uint32_t v_[4][4];
            #pragma unroll
            for (int g = 0; g < 4; g++) {
                uint32_t off = rowOff + g * 32;
                ldsm_x4_t(v_[g], uV_ + off);
            }
            #pragma unroll
            for (int g = 0; g < 4; g++) {
                mma_f16(O[2 * g],     aP[t], v_[g]);
                mma_f16(O[2 * g + 1], aP[t], v_[g] + 2);
            }
        }

        __syncthreads();
        if (kt + 2 < 32) issue(kt + 2, stage);
    }

    l0 += __shfl_xor_sync(0xffffffffu, l0, 1);
    l0 += __shfl_xor_sync(0xffffffffu, l0, 2);
    l1 += __shfl_xor_sync(0xffffffffu, l1, 1);
    l1 += __shfl_xor_sync(0xffffffffu, l1, 2);
    float inv0 = 1.0f / l0, inv1 = 1.0f / l1;

    const int b = bh >> 4, h = bh & 15;
    const int qr = qt * 128 + w * 16 + (lane >> 2);
    #pragma unroll
    for (int j = 0; j < 8; j++) {
        int col = h * HDIM + j * 8 + colOff;
        *(__half2*)(ctx16 + (size_t)(b * SEQ + qr) * DMODEL + col) =
            __floats2half2_rn(O[j][0] * inv0, O[j][1] * inv0);
        *(__half2*)(ctx16 + (size_t)(b * SEQ + qr + 8) * DMODEL + col) =
            __floats2half2_rn(O[j][2] * inv1, O[j][3] * inv1);
    }
}

// ---------------------------------------------------------------------------
// Launch
// ---------------------------------------------------------------------------
extern "C" void kernel_launch(void* const* d_in, const int* in_sizes, int n_in,
                              void* d_out, int out_size)
{
    const float* x    = (const float*)d_in[0];
    const int*   mask = (const int*)  d_in[1];
    const float* Wq   = (const float*)d_in[2];
    const float* bq   = (const float*)d_in[3];
    const float* Wk   = (const float*)d_in[4];
    const float* bk   = (const float*)d_in[5];
    const float* Wv   = (const float*)d_in[6];
    const float* bv   = (const float*)d_in[7];
    const float* Wo   = (const float*)d_in[8];
    const float* bo   = (const float*)d_in[9];
    float* out = (float*)d_out;

    __half *x16, *wth, *q16, *k16, *v16, *ctx16;
    float* bias3;
    uint32_t* mbits;
    cudaGetSymbolAddress((void**)&x16,  g_x16);
    cudaGetSymbolAddress((void**)&wth,  g_WTh);
    cudaGetSymbolAddress((void**)&bias3, g_bias3);
    cudaGetSymbolAddress((void**)&q16,  g_Q16);
    cudaGetSymbolAddress((void**)&k16,  g_K16);
    cudaGetSymbolAddress((void**)&v16,  g_V16);
    cudaGetSymbolAddress((void**)&ctx16, g_ctx16);
    cudaGetSymbolAddress((void**)&mbits, g_maskbits);

    cudaFuncSetAttribute(mm1, cudaFuncAttributeMaxDynamicSharedMemorySize, MM1_SMEM);
    cudaFuncSetAttribute(flash_mma, cudaFuncAttributeMaxDynamicSharedMemorySize, FLASH_SMEM);

    to_half8<<<(MTOT * DMODEL) / (256 * 8), 256>>>(x, x16);
    transpose4<<<dim3(32, 32, 4), dim3(32, 8)>>>(Wq, Wk, Wv, Wo, wth);
    concat_bias<<<4, 256>>>(bq, bk, bv, bias3);
    mask_pack<<<(SEQ * SEQ) / (256 * 128 / 32), 256>>>(mask, mbits);

    // QKV fused: N = 3072
    mm1<<<dim3(24, 32), 512, MM1_SMEM>>>(x16, wth, bias3, 1, nullptr, q16, k16, v16);

    flash_mma<<<dim3(SEQ / 128, BATCH * NHEADS), 256, FLASH_SMEM>>>(
        q16, k16, v16, mbits, ctx16);

    // O projection: N = 1024
    mm1<<<dim3(8, 32), 512, MM1_SMEM>>>(ctx16,
        wth + 3 * (size_t)DMODEL * DMODEL, bo, 0, out, nullptr, nullptr, nullptr);
}

// round 17
// speedup vs baseline: 1.5005x; 1.5005x over previous
#include <cuda_runtime.h>
#include <cuda_fp16.h>
#include <cstdint>

#define BATCH 2
#define SEQ 2048
#define DMODEL 1024
#define NHEADS 16
#define HDIM 64
#define MTOT (BATCH * SEQ)          // 4096

#define WSCALE 2048.0f
#define INV_WSCALE 4.8828125e-4f    // 2^-11

// ---------------------------------------------------------------------------
// Scratch (static device globals)
// ---------------------------------------------------------------------------
__device__ __align__(16) __half g_x16[MTOT * DMODEL];
__device__ __align__(16) __half g_WTh[4][DMODEL * DMODEL];         // (2048 W)^T fp16
__device__ __align__(16) float  g_bias3[3 * DMODEL];
__device__ __align__(16) __half g_Q16[BATCH * NHEADS * SEQ * HDIM];  // [B,H,S,Dh]
__device__ __align__(16) __half g_K16[BATCH * NHEADS * SEQ * HDIM];
__device__ __align__(16) __half g_V16[BATCH * NHEADS * SEQ * HDIM];
__device__ __align__(16) __half g_ctx16[MTOT * DMODEL];            // [B,S,D] fp16
__device__ __align__(16) uint32_t g_maskbits[SEQ * (SEQ / 32)];    // 1 bit/elem, 512 KB

// ---------------------------------------------------------------------------
// Helpers
// ---------------------------------------------------------------------------
__device__ __forceinline__ uint32_t smem_u32(const void* p) {
    uint32_t a;
    asm("{ .reg .u64 t; cvta.to.shared.u64 t, %1; cvt.u32.u64 %0, t; }" : "=r"(a) : "l"(p));
    return a;
}
__device__ __forceinline__ void ldsm_x4(uint32_t* r, uint32_t addr) {
    asm volatile("ldmatrix.sync.aligned.m8n8.x4.shared.b16 {%0,%1,%2,%3}, [%4];"
        : "=r"(r[0]), "=r"(r[1]), "=r"(r[2]), "=r"(r[3]) : "r"(addr));
}
__device__ __forceinline__ void ldsm_x4_t(uint32_t* r, uint32_t addr) {
    asm volatile("ldmatrix.sync.aligned.m8n8.x4.trans.shared.b16 {%0,%1,%2,%3}, [%4];"
        : "=r"(r[0]), "=r"(r[1]), "=r"(r[2]), "=r"(r[3]) : "r"(addr));
}
__device__ __forceinline__ void mma_f16(float* d, const uint32_t* a, const uint32_t* b) {
    asm volatile("mma.sync.aligned.m16n8k16.row.col.f32.f16.f16.f32 "
        "{%0,%1,%2,%3}, {%4,%5,%6,%7}, {%8,%9}, {%0,%1,%2,%3};"
        : "+f"(d[0]), "+f"(d[1]), "+f"(d[2]), "+f"(d[3])
        : "r"(a[0]), "r"(a[1]), "r"(a[2]), "r"(a[3]), "r"(b[0]), "r"(b[1]));
}
__device__ __forceinline__ uint32_t h2exp2(uint32_t x) {
    uint32_t r;
    asm volatile("ex2.approx.f16x2 %0, %1;" : "=r"(r) : "r"(x));
    return r;
}
#define CP_ASYNC16(dst_u32, src_gptr) \
    asm volatile("cp.async.cg.shared.global [%0], [%1], 16;" \
        :: "r"(dst_u32), "l"(__cvta_generic_to_global(src_gptr)) : "memory")
#define CP_COMMIT() asm volatile("cp.async.commit_group;" ::: "memory")
#define CP_WAIT1()  asm volatile("cp.async.wait_group 1;" ::: "memory")
#define CP_WAIT0()  asm volatile("cp.async.wait_group 0;" ::: "memory")

// ---------------------------------------------------------------------------
// Prep kernels (vectorized — R16 versions, kept)
// ---------------------------------------------------------------------------
__global__ void to_half8(const float* __restrict__ X, __half* __restrict__ X16)
{
    int i = (blockIdx.x * blockDim.x + threadIdx.x) * 8;
    float4 f0 = *(const float4*)(X + i);
    float4 f1 = *(const float4*)(X + i + 4);
    __half2 h[4];
    h[0] = __floats2half2_rn(f0.x, f0.y);
    h[1] = __floats2half2_rn(f0.z, f0.w);
    h[2] = __floats2half2_rn(f1.x, f1.y);
    h[3] = __floats2half2_rn(f1.z, f1.w);
    *(uint4*)(X16 + i) = *(uint4*)h;
}

__global__ void transpose4(const float* __restrict__ W0, const float* __restrict__ W1,
                           const float* __restrict__ W2, const float* __restrict__ W3,
                           __half* __restrict__ ThBase)
{
    __shared__ float t[32][33];
    const int z = blockIdx.z;
    const float* W = (z == 0) ? W0 : (z == 1) ? W1 : (z == 2) ? W2 : W3;
    __half* Th = ThBase + (size_t)z * DMODEL * DMODEL;
    int bx = blockIdx.x * 32;
    int by = blockIdx.y * 32;
    int tx = threadIdx.x, ty = threadIdx.y;
    #pragma unroll
    for (int i = 0; i < 4; i++)
        t[ty + i * 8][tx] = W[(size_t)(by + ty + i * 8) * DMODEL + bx + tx];
    __syncthreads();
    #pragma unroll
    for (int i = 0; i < 4; i++) {
        float v = t[tx][ty + i * 8] * WSCALE;
        size_t o = (size_t)(bx + ty + i * 8) * DMODEL + by + tx;
        Th[o] = __float2half(v);
    }
}

__global__ void concat_bias(const float* __restrict__ a, const float* __restrict__ b,
                            const float* __restrict__ c, float* __restrict__ o)
{
    int i = blockIdx.x * blockDim.x + threadIdx.x;
    if (i < DMODEL) { o[i] = a[i]; o[i + DMODEL] = b[i]; o[i + 2 * DMODEL] = c[i]; }
}

// Pack int32 mask -> 1 bit/elem. One warp packs 128 elems via 4 coalesced ballots.
__global__ void mask_pack(const int* __restrict__ mask, uint32_t* __restrict__ bits)
{
    int gw = (blockIdx.x * blockDim.x + threadIdx.x) >> 5;
    int lane = threadIdx.x & 31;
    const int* p = mask + (size_t)gw * 128;
    uint32_t b0 = __ballot_sync(0xffffffffu, p[lane]      != 0);
    uint32_t b1 = __ballot_sync(0xffffffffu, p[lane + 32] != 0);
    uint32_t b2 = __ballot_sync(0xffffffffu, p[lane + 64] != 0);
    uint32_t b3 = __ballot_sync(0xffffffffu, p[lane + 96] != 0);
    if (lane == 0) {
        uint4 v; v.x = b0; v.y = b1; v.z = b2; v.w = b3;
        *(uint4*)(bits + (size_t)gw * 4) = v;
    }
}

// ---------------------------------------------------------------------------
// fp16 single-term GEMM (scaled) — R15 proven config:
// 256 threads, warp tile 32x64, K-chunk 32, 2-stage cp.async, 2 CTA/SM.
// acc = A16 @ BTh^T (= 2048*A W^T); epilogue C = acc * 2^-11 + bias.
// ---------------------------------------------------------------------------
#define MKS 40
#define ARRB (128 * MKS * 2)                // 10240 B
#define MM1_SMEM (2 * 2 * ARRB)             // 40960 B

__global__ __launch_bounds__(256, 2)
void mm1(const __half* __restrict__ A16, const __half* __restrict__ BTh,
         const float* __restrict__ bias, int mode, float* __restrict__ Cf,
         __half* __restrict__ oQ, __half* __restrict__ oK, __half* __restrict__ oV)
{
    extern __shared__ char sm[];
    const uint32_t sb = smem_u32(sm);

    const int tid = threadIdx.x;
    const int wid = tid >> 5;
    const int lane = tid & 31;
    const int wm = wid & 3;
    const int wn = wid >> 2;
    const int bm = blockIdx.y * 128;
    const int bn = blockIdx.x * 128;

    const int wsel = bn >> 10;
    const __half* Bh = BTh + (size_t)wsel * DMODEL * DMODEL;
    const int rB = bn & 1023;

    int rr[2], sg[2];
    #pragma unroll
    for (int u = 0; u < 2; u++) { int lin = tid * 2 + u; rr[u] = lin >> 2; sg[u] = lin & 3; }

    auto issue = [&](int c, int st) {
        const int k0 = c * 32;
        #pragma unroll
        for (int u = 0; u < 2; u++) {
            uint32_t so = (rr[u] * MKS + sg[u] * 8) * 2;
            uint32_t dst = sb + st * 2 * ARRB + so;
            size_t ga = (size_t)(bm + rr[u]) * DMODEL + k0 + sg[u] * 8;
            size_t gb = (size_t)(rB + rr[u]) * DMODEL + k0 + sg[u] * 8;
            CP_ASYNC16(dst + 0 * ARRB, A16 + ga);
            CP_ASYNC16(dst + 1 * ARRB, Bh + gb);
        }
        CP_COMMIT();
    };

    issue(0, 0);
    issue(1, 1);

    float acc[2][8][4];
    #pragma unroll
    for (int mi = 0; mi < 2; mi++)
        #pragma unroll
        for (int ni = 0; ni < 8; ni++)
            #pragma unroll
            for (int e = 0; e < 4; e++) acc[mi][ni][e] = 0.0f;

    const int aRow = wm * 32 + (lane & 15);
    const int aK   = (lane >> 4) * 8;
    const int bRow = wn * 64 + ((lane >> 4) & 1) * 8 + (lane & 7);
    const int bK   = ((lane >> 3) & 1) * 8;

    const int NCH = DMODEL / 32;   // 32
    for (int c = 0; c < NCH; c++) {
        const int st = c & 1;
        if (c + 1 < NCH) { CP_WAIT1(); } else { CP_WAIT0(); }
        __syncthreads();

        const uint32_t uA  = sb + st * 2 * ARRB + 0 * ARRB;
        const uint32_t uBh = sb + st * 2 * ARRB + 1 * ARRB;

        #pragma unroll
        for (int s = 0; s < 2; s++) {
            uint32_t aF[2][4];
            #pragma unroll
            for (int mi = 0; mi < 2; mi++) {
                uint32_t off = ((aRow + mi * 16) * MKS + s * 16 + aK) * 2;
                ldsm_x4(aF[mi], uA + off);
            }
            #pragma unroll
            for (int gh = 0; gh < 2; gh++) {
                uint32_t bH[2][4];
                #pragma unroll
                for (int j = 0; j < 2; j++) {
                    uint32_t off = ((bRow + (2 * gh + j) * 16) * MKS + s * 16 + bK) * 2;
                    ldsm_x4(bH[j], uBh + off);
                }
                #pragma unroll
                for (int mi = 0; mi < 2; mi++)
                    #pragma unroll
                    for (int j = 0; j < 2; j++) {
                        mma_f16(acc[mi][4 * gh + 2 * j],     aF[mi], bH[j]);
                        mma_f16(acc[mi][4 * gh + 2 * j + 1], aF[mi], bH[j] + 2);
                    }
            }
        }

        __syncthreads();
        if (c + 2 < NCH) issue(c + 2, st);
    }

    // Epilogue
    const int rBase = bm + wm * 32 + (lane >> 2);
    const int cBase = bn + wn * 64 + (lane & 3) * 2;
    #pragma unroll
    for (int mi = 0; mi < 2; mi++) {
        #pragma unroll
        for (int ni = 0; ni < 8; ni++) {
            int col = cBase + ni * 8;
            float b0 = bias[col], b1 = bias[col + 1];
            #pragma unroll
            for (int half_ = 0; half_ < 2; half_++) {
                int m = rBase + mi * 16 + half_ * 8;
                float v0 = acc[mi][ni][half_ * 2 + 0] * INV_WSCALE + b0;
                float v1 = acc[mi][ni][half_ * 2 + 1] * INV_WSCALE + b1;
                if (mode) {
                    int n1 = col & 1023;
                    int b = m >> 11, s = m & 2047;
                    int h = n1 >> 6, d = n1 & 63;
                    size_t o = ((size_t)((b << 4) + h) * SEQ + s) * HDIM + d;
                    __half* dst = (wsel == 0) ? oQ : (wsel == 1) ? oK : oV;
                    *(__half2*)(dst + o) = __floats2half2_rn(v0, v1);
                } else {
                    float* dst = Cf + (size_t)m * DMODEL + col;
                    dst[0] = v0; dst[1] = v1;
                }
            }
        }
    }
}

// ---------------------------------------------------------------------------
// Flash attention (R15): fp16 single-term, fixed-max f16x2-EX2 softmax,
// bit-packed mask, 2-stage cp.async, 2 CTA/SM.
// ---------------------------------------------------------------------------
#define FSTR 72
#define FROWB (FSTR * 2)
#define FT_BYTES (64 * FSTR * 2)            // 9216
#define FLASH_SMEM (2 * 2 * FT_BYTES)       // 36864
#define SCALE_LOG2E 0.18033688011112042f    // 0.125 * log2(e)
#define MWORDS (SEQ / 32)                   // 64 words per row

__global__ __launch_bounds__(256, 2)
void flash_mma(const __half* __restrict__ Q16,
               const __half* __restrict__ K16, const __half* __restrict__ V16,
               const uint32_t* __restrict__ mbits, __half* __restrict__ ctx16)
{
    extern __shared__ char sm[];
    const uint32_t uKV = smem_u32(sm);

    const int tid = threadIdx.x;
    const int lane = tid & 31;
    const int w = tid >> 5;
    const int qt = blockIdx.x;
    const int bh = blockIdx.y;
    const size_t base = (size_t)bh * SEQ * HDIM;

    // Q overlay through stage buffers
    #pragma unroll
    for (int i = 0; i < 4; i++) {
        int lin = tid + i * 256;
        int r = lin >> 3, c = lin & 7;
        *(uint4*)(sm + r * FROWB + c * 16) =
            *(const uint4*)&Q16[base + (size_t)(qt * 128 + r) * HDIM + c * 8];
    }
    __syncthreads();

    uint32_t qf[4][4];
    #pragma unroll
    for (int kch = 0; kch < 4; kch++) {
        uint32_t off = (w * 16 + (lane & 15)) * FROWB + (kch * 16 + (lane >> 4) * 8) * 2;
        ldsm_x4(qf[kch], uKV + off);
    }
    __syncthreads();

    const __half* srcs[2] = { K16, V16 };
    auto issue = [&](int kt, int stage) {
        #pragma unroll
        for (int t = 0; t < 2; t++) {
            #pragma unroll
            for (int u = 0; u < 2; u++) {
                int lin = tid * 2 + u;
                int r = lin >> 3, c = lin & 7;
                uint32_t dst = uKV + (stage * 2 + t) * FT_BYTES + r * FROWB + c * 16;
                const __half* src = srcs[t] + base + (size_t)(kt * 64 + r) * HDIM + c * 8;
                CP_ASYNC16(dst, src);
            }
        }
        CP_COMMIT();
    };

    issue(0, 0);
    issue(1, 1);

    float O[8][4];
    #pragma unroll
    for (int j = 0; j < 8; j++)
        #pragma unroll
        for (int e = 0; e < 4; e++) O[j][e] = 0.0f;
    float l0 = 0.0f, l1 = 0.0f;

    const int q0 = qt * 128 + w * 16 + (lane >> 2);
    const int colOff = 2 * (lane & 3);
    const uint32_t* mrowA = mbits + (size_t)q0 * MWORDS;
    const uint32_t* mrowB = mbits + (size_t)(q0 + 8) * MWORDS;

    for (int kt = 0; kt < 32; kt++) {
        const int stage = kt & 1;
        if (kt + 1 < 32) { CP_WAIT1(); } else { CP_WAIT0(); }
        __syncthreads();

        const uint32_t uK_ = uKV + (stage * 2 + 0) * FT_BYTES;
        const uint32_t uV_ = uKV + (stage * 2 + 1) * FT_BYTES;

        float S[8][4];
        #pragma unroll
        for (int j = 0; j < 8; j++)
            #pragma unroll
            for (int e = 0; e < 4; e++) S[j][e] = 0.0f;

        const int rowN = ((lane >> 4) & 1) * 8 + (lane & 7);
        const int bKo  = ((lane >> 3) & 1) * 16;
        #pragma unroll
        for (int kch = 0; kch < 4; kch++) {
            uint32_t bk_[4][4];
            #pragma unroll
            for (int g = 0; g < 4; g++) {
                uint32_t off = (g * 16 + rowN) * FROWB + kch * 32 + bKo;
                ldsm_x4(bk_[g], uK_ + off);
            }
            #pragma unroll
            for (int g = 0; g < 4; g++) {
                mma_f16(S[2 * g],     qf[kch], bk_[g]);
                mma_f16(S[2 * g + 1], qf[kch], bk_[g] + 2);
            }
        }

        const uint32_t mA0 = mrowA[2 * kt], mA1 = mrowA[2 * kt + 1];
        const uint32_t mB0 = mrowB[2 * kt], mB1 = mrowB[2 * kt + 1];

        uint32_t aP[4][4];
        #pragma unroll
        for (int j = 0; j < 8; j++) {
            const uint32_t mAw = (j < 4) ? mA0 : mA1;
            const uint32_t mBw = (j < 4) ? mB0 : mB1;
            const int bit = (j & 3) * 8 + colOff;
            float f0 = ((mAw >> bit) & 1u)       ? S[j][0] * SCALE_LOG2E : -1e4f;
            float f1 = ((mAw >> (bit + 1)) & 1u) ? S[j][1] * SCALE_LOG2E : -1e4f;
            float f2 = ((mBw >> bit) & 1u)       ? S[j][2] * SCALE_LOG2E : -1e4f;
            float f3 = ((mBw >> (bit + 1)) & 1u) ? S[j][3] * SCALE_LOG2E : -1e4f;
            __half2 a01 = __floats2half2_rn(f0, f1);
            __half2 a23 = __floats2half2_rn(f2, f3);
            uint32_t p01 = h2exp2(*(uint32_t*)&a01);
            uint32_t p23 = h2exp2(*(uint32_t*)&a23);
            const int t = j >> 1, u = j & 1;
            aP[t][2 * u]     = p01;
            aP[t][2 * u + 1] = p23;
            float2 g01 = __half22float2(*(__half2*)&p01);
            float2 g23 = __half22float2(*(__half2*)&p23);
            l0 += g01.x + g01.y;
            l1 += g23.x + g23.y;
        }

        #pragma unroll
        for (int t = 0; t < 4; t++) {
            uint32_t rowOff = (t * 16 + (lane & 15)) * FROWB + (lane >> 4) * 16;
            uint32_t v_[4][4];
            #pragma unroll
            for (int g = 0; g < 4; g++) {
                uint32_t off = rowOff + g * 32;
                ldsm_x4_t(v_[g], uV_ + off);
            }
            #pragma unroll
            for (int g = 0; g < 4; g++) {
                mma_f16(O[2 * g],     aP[t], v_[g]);
                mma_f16(O[2 * g + 1], aP[t], v_[g] + 2);
            }
        }

        __syncthreads();
        if (kt + 2 < 32) issue(kt + 2, stage);
    }

    l0 += __shfl_xor_sync(0xffffffffu, l0, 1);
    l0 += __shfl_xor_sync(0xffffffffu, l0, 2);
    l1 += __shfl_xor_sync(0xffffffffu, l1, 1);
    l1 += __shfl_xor_sync(0xffffffffu, l1, 2);
    float inv0 = 1.0f / l0, inv1 = 1.0f / l1;

    const int b = bh >> 4, h = bh & 15;
    const int qr = qt * 128 + w * 16 + (lane >> 2);
    #pragma unroll
    for (int j = 0; j < 8; j++) {
        int col = h * HDIM + j * 8 + colOff;
        *(__half2*)(ctx16 + (size_t)(b * SEQ + qr) * DMODEL + col) =
            __floats2half2_rn(O[j][0] * inv0, O[j][1] * inv0);
        *(__half2*)(ctx16 + (size_t)(b * SEQ + qr + 8) * DMODEL + col) =
            __floats2half2_rn(O[j][2] * inv1, O[j][3] * inv1);
    }
}

// ---------------------------------------------------------------------------
// Launch
// ---------------------------------------------------------------------------
extern "C" void kernel_launch(void* const* d_in, const int* in_sizes, int n_in,
                              void* d_out, int out_size)
{
    const float* x    = (const float*)d_in[0];
    const int*   mask = (const int*)  d_in[1];
    const float* Wq   = (const float*)d_in[2];
    const float* bq   = (const float*)d_in[3];
    const float* Wk   = (const float*)d_in[4];
    const float* bk   = (const float*)d_in[5];
    const float* Wv   = (const float*)d_in[6];
    const float* bv   = (const float*)d_in[7];
    const float* Wo   = (const float*)d_in[8];
    const float* bo   = (const float*)d_in[9];
    float* out = (float*)d_out;

    __half *x16, *wth, *q16, *k16, *v16, *ctx16;
    float* bias3;
    uint32_t* mbits;
    cudaGetSymbolAddress((void**)&x16,  g_x16);
    cudaGetSymbolAddress((void**)&wth,  g_WTh);
    cudaGetSymbolAddress((void**)&bias3, g_bias3);
    cudaGetSymbolAddress((void**)&q16,  g_Q16);
    cudaGetSymbolAddress((void**)&k16,  g_K16);
    cudaGetSymbolAddress((void**)&v16,  g_V16);
    cudaGetSymbolAddress((void**)&ctx16, g_ctx16);
    cudaGetSymbolAddress((void**)&mbits, g_maskbits);

    cudaFuncSetAttribute(mm1, cudaFuncAttributeMaxDynamicSharedMemorySize, MM1_SMEM);
    cudaFuncSetAttribute(flash_mma, cudaFuncAttributeMaxDynamicSharedMemorySize, FLASH_SMEM);

    to_half8<<<(MTOT * DMODEL) / (256 * 8), 256>>>(x, x16);
    transpose4<<<dim3(32, 32, 4), dim3(32, 8)>>>(Wq, Wk, Wv, Wo, wth);
    concat_bias<<<4, 256>>>(bq, bk, bv, bias3);
    mask_pack<<<(SEQ * SEQ) / (256 * 128 / 32), 256>>>(mask, mbits);

    // QKV fused: N = 3072
    mm1<<<dim3(24, 32), 256, MM1_SMEM>>>(x16, wth, bias3, 1, nullptr, q16, k16, v16);

    flash_mma<<<dim3(SEQ / 128, BATCH * NHEADS), 256, FLASH_SMEM>>>(
        q16, k16, v16, mbits, ctx16);

    // O projection: N = 1024
    mm1<<<dim3(8, 32), 256, MM1_SMEM>>>(ctx16,
        wth + 3 * (size_t)DMODEL * DMODEL, bo, 0, out, nullptr, nullptr, nullptr);
}